// round 16
// baseline (speedup 1.0000x reference)
#include <cuda_runtime.h>
#include <cuda_bf16.h>
#include <cuda_fp16.h>
#include <math.h>

// Problem constants (LocalSubgraphTransformer)
#define S_   2048
#define K_   32
#define H_   256
#define NH_  8
#define DH_  32
#define L_   4
#define ED_  16
#define FFN_ 512
#define EPS_ 64
#define E_   (S_*EPS_)

#define THREADS 512

#define LDA2 520    // XN2 row stride (fp16): hi 256 | lo 256 | pad 8
#define LDB2 1032   // BUF2 row stride (fp16): hi 512 | lo 512 | pad 8
#define LDQ  772    // qkv fp32 row stride

// ---------------- device scratch ----------------
__device__ __nv_bfloat16 g_bias16[(size_t)S_ * NH_ * K_ * K_];   // [S][h][k][q]
// weights in mma B-fragment order, single fp16: N*KA fp16 = N*KA/2 u32 words
__device__ unsigned g_w2_qkv[(size_t)L_ * 768 * 128];
__device__ unsigned g_w2_out[(size_t)L_ * 256 * 128];
__device__ unsigned g_w2_ff1[(size_t)L_ * 512 * 128];
__device__ unsigned g_w2_ff2[(size_t)L_ * 256 * 256];

// ---------------------------------------------------------------------------
// Weight conversion: fp32 [L][N][KA] row-major -> fp16 B-fragment layout.
// Unit (16 B = 4 words) uid = (((pass*T + kt)*8 + ng)*2 + j)*32 + lane
//   n = pass*128 + ng*16 + j*8 + (lane>>2)
//   word w: k = kt*32 + (w>>1)*16 + (lane&3)*2 + (w&1)*8, covers {k, k+1}
// ---------------------------------------------------------------------------
__global__ void wconv_frag(const float* __restrict__ src, uint4* __restrict__ dst,
                           int N, int KA, int total_units)
{
    const int e = blockIdx.x*256 + threadIdx.x;
    if (e >= total_units) return;
    const int UPL = N*KA/8;            // units per layer
    const int l = e / UPL;
    int u = e - l*UPL;
    const int lane = u & 31; u >>= 5;
    const int j = u & 1; u >>= 1;
    const int ng = u & 7; u >>= 3;
    const int T = KA/32;
    const int kt = u % T;
    const int pass = u / T;
    const int n = pass*128 + ng*16 + j*8 + (lane>>2);
    const float* sp = src + ((size_t)l*N + n)*KA;

    unsigned words[4];
    #pragma unroll
    for (int w = 0; w < 4; w++) {
        const int k = kt*32 + (w>>1)*16 + (lane&3)*2 + (w&1)*8;
        const __half v0 = __float2half(sp[k]);
        const __half v1 = __float2half(sp[k+1]);
        unsigned lo16 = (unsigned)*(const unsigned short*)&v0;
        unsigned hi16 = (unsigned)*(const unsigned short*)&v1;
        words[w] = lo16 | (hi16 << 16);
    }
    dst[e] = make_uint4(words[0], words[1], words[2], words[3]);
}

// ---------------------------------------------------------------------------
// Kernel A: per-subgraph edge bias via shared-memory scatter-add
// ---------------------------------------------------------------------------
__global__ __launch_bounds__(256) void edge_bias_kernel(
    const float* __restrict__ ea, const int* __restrict__ eidx,
    const float* __restrict__ eW, const float* __restrict__ eb)
{
    __shared__ float sb[NH_*K_*K_];   // [h][dst=k][src=q]
    __shared__ float sa[EPS_*ED_];
    __shared__ float sw[NH_*ED_];
    __shared__ float sbv[NH_];
    const int s = blockIdx.x, tid = threadIdx.x;

    if (tid < NH_*ED_) sw[tid] = eW[tid];
    if (tid < NH_)     sbv[tid] = eb[tid];
    for (int i = tid; i < EPS_*ED_;  i += 256) sa[i] = ea[(size_t)s*EPS_*ED_ + i];
    for (int i = tid; i < NH_*K_*K_; i += 256) sb[i] = 0.f;
    __syncthreads();

    for (int t = tid; t < EPS_*NH_; t += 256) {
        const int i  = t >> 3;
        const int hh = t & 7;
        float p = sbv[hh];
        #pragma unroll
        for (int d = 0; d < ED_; d++) p = fmaf(sa[i*ED_+d], sw[hh*ED_+d], p);
        const int e  = s*EPS_ + i;
        const int sr = eidx[e];        // src = query index
        const int ds = eidx[E_ + e];   // dst = key index
        atomicAdd(&sb[hh*K_*K_ + ds*K_ + sr], p);
    }
    __syncthreads();
    for (int i = tid; i < NH_*K_*K_; i += 256)
        g_bias16[(size_t)s*NH_*K_*K_ + i] = __float2bfloat16(sb[i]);
}

// ---------------------------------------------------------------------------
// smem layout (float offsets)
// ---------------------------------------------------------------------------
#define OFF_X    0        /* 8192 f: X fp32 [32][256] */
#define OFF_BUF  8192     /* 24704 f: union { fp32 [32][772] qkv ; fp16 [32][1032] ffn2 } */
#define OFF_XN2  32896    /* 8320 f: fp16 [32][520] */
#define OFF_BS   41216    /* 4096 f: bf16 [8][32][32] */
#define OFF_KM   45312
#define OFF_V01  45344
#define SMEM_FLOATS 45376  /* 181504 bytes */

__device__ __forceinline__ unsigned sptr(const void* p) {
    return (unsigned)__cvta_generic_to_shared(p);
}
__device__ __forceinline__ void ldm_x4(unsigned& a0, unsigned& a1, unsigned& a2,
                                       unsigned& a3, unsigned addr) {
    asm volatile("ldmatrix.sync.aligned.m8n8.x4.shared.b16 {%0,%1,%2,%3},[%4];"
                 : "=r"(a0), "=r"(a1), "=r"(a2), "=r"(a3) : "r"(addr));
}
__device__ __forceinline__ void mma16816h(float* c, const unsigned* a,
                                          unsigned b0, unsigned b1) {
    asm volatile("mma.sync.aligned.m16n8k16.row.col.f32.f16.f16.f32 "
                 "{%0,%1,%2,%3},{%4,%5,%6,%7},{%8,%9},{%0,%1,%2,%3};"
                 : "+f"(c[0]), "+f"(c[1]), "+f"(c[2]), "+f"(c[3])
                 : "r"(a[0]), "r"(a[1]), "r"(a[2]), "r"(a[3]), "r"(b0), "r"(b1));
}
__device__ __forceinline__ void hilo16(float v, __half& hi, __half& lo) {
    hi = __float2half(v);
    lo = __float2half(v - __half2float(hi));
}

// ---------------------------------------------------------------------------
// Tensor-core GEMM: C = (A_hi + A_lo) W^T + bias, fp16 operands, fp32 accum.
// 16 warps: mi = wid & 1 (m16 group), ng = wid >> 1 (n16 group). Per n128
// pass a warp computes rows mi*16..+15, cols ng*16..+15.
// A fragments: full m16xk16 via ldmatrix.x4 (proven R14 address pattern),
// separately for hi and lo components. 4 x ldm.x4 + 8 mma per kt.
// B: 4-slot register ring over global step = pass*T + kt (pipelines passes).
// MODE 0: fp32 -> BUFf (ld LDQ); 1: relu -> hi/lo BUF2; 2: += X (ld H_)
// ---------------------------------------------------------------------------
template<int N, int KA, int MODE>
__device__ __forceinline__ void mm3(const __half* A, int lda,
    const uint4* __restrict__ Wf, const float* __restrict__ bias,
    float* Xd, float* BUFf, __half* BUF2, int tid)
{
    const int lane = tid & 31, wid = tid >> 5;
    const int mi = wid & 1, ng = wid >> 1;
    constexpr int T = KA/32;          // k32 stages per pass
    constexpr int P = N/128;          // passes
    constexpr int TOT = P*T;          // global steps
    // A ldmatrix base: row = mi*16 + (lane&15), 16B col = lane>>4
    const unsigned a_s = sptr(A) +
        (unsigned)(((mi*16 + (lane & 15))*lda + ((lane >> 4) << 3))*2);

    // 4-slot B ring (T is 8 or 16, multiple of 4 -> slot = step & 3 consistent)
    uint4 ring[4][2];
    #define LDB_G(sg, slot) do {                                          \
        if ((sg) < TOT) {                                                 \
            const size_t _b = ((size_t)((sg)*8 + ng)*2)*32 + lane;        \
            ring[slot][0] = Wf[_b];  ring[slot][1] = Wf[_b + 32];         \
        }                                                                 \
    } while (0)

    LDB_G(0, 0); LDB_G(1, 1); LDB_G(2, 2); LDB_G(3, 3);

    for (int pass = 0; pass < P; pass++) {
        float acc[2][4];   // [j][4]
        #pragma unroll
        for (int j = 0; j < 2; j++)
            #pragma unroll
            for (int i = 0; i < 4; i++) acc[j][i] = 0.f;

        const int g0 = pass*T;
        #pragma unroll
        for (int kt = 0; kt < T; kt++) {
            // A fragments: [ks] hi and lo, each full m16xk16 (ldm.x4)
            unsigned ah[2][4], al[2][4];
            #pragma unroll
            for (int ks = 0; ks < 2; ks++) {
                const unsigned base = a_s + (unsigned)((kt*32 + ks*16)*2);
                ldm_x4(ah[ks][0], ah[ks][1], ah[ks][2], ah[ks][3], base);
                ldm_x4(al[ks][0], al[ks][1], al[ks][2], al[ks][3],
                       base + (unsigned)(KA*2));
            }
            const uint4* b = ring[(g0 + kt) & 3];
            // 8 mma: ks x j x (hi, lo)
            #pragma unroll
            for (int ks = 0; ks < 2; ks++) {
                const unsigned w0 = ks ? b[0].z : b[0].x;
                const unsigned w1 = ks ? b[0].w : b[0].y;
                const unsigned w2 = ks ? b[1].z : b[1].x;
                const unsigned w3 = ks ? b[1].w : b[1].y;
                mma16816h(acc[0], ah[ks], w0, w1);
                mma16816h(acc[1], ah[ks], w2, w3);
                mma16816h(acc[0], al[ks], w0, w1);
                mma16816h(acc[1], al[ks], w2, w3);
            }
            LDB_G(g0 + kt + 4, (g0 + kt) & 3);
        }
        // epilogue
        #pragma unroll
        for (int j = 0; j < 2; j++) {
            const int c = pass*128 + ng*16 + j*8 + 2*(lane & 3);
            const float bb0 = bias[c], bb1 = bias[c+1];
            #pragma unroll
            for (int rr = 0; rr < 2; rr++) {
                const int r = mi*16 + (lane >> 2) + rr*8;
                float v0 = acc[j][rr*2+0] + bb0;
                float v1 = acc[j][rr*2+1] + bb1;
                if (MODE == 0) {
                    BUFf[r*LDQ + c]   = v0;
                    BUFf[r*LDQ + c+1] = v1;
                } else if (MODE == 2) {
                    Xd[r*H_ + c]   += v0;
                    Xd[r*H_ + c+1] += v1;
                } else {
                    v0 = fmaxf(v0, 0.f); v1 = fmaxf(v1, 0.f);
                    __half h0, l0, h1, l1;
                    hilo16(v0, h0, l0); hilo16(v1, h1, l1);
                    __half* d = BUF2 + r*LDB2;
                    d[c] = h0;       d[c+1] = h1;
                    d[512 + c] = l0; d[512 + c+1] = l1;
                }
            }
        }
    }
    #undef LDB_G
}

// ---------------------------------------------------------------------------
// LayerNorm over 32 rows (16 warps, 2 rows each).
// OM 0: fp32 dst (ld H_); OM 1: hi/lo fp16 (ld LDA2)
// ---------------------------------------------------------------------------
template<int OM>
__device__ __forceinline__ void ln32(const float* src, void* dstv,
                                     const float* __restrict__ g,
                                     const float* __restrict__ b, int tid)
{
    const int w = tid >> 5, lane = tid & 31;
    #pragma unroll
    for (int j = 0; j < 2; j++) {
        const int r = w*2 + j;
        float sum = 0.f, sq = 0.f;
        #pragma unroll
        for (int i = 0; i < 8; i++) {
            const float v = src[r*H_ + lane + i*32];
            sum += v; sq = fmaf(v, v, sq);
        }
        #pragma unroll
        for (int o = 16; o > 0; o >>= 1) {
            sum += __shfl_xor_sync(0xffffffffu, sum, o);
            sq  += __shfl_xor_sync(0xffffffffu, sq,  o);
        }
        const float mu   = sum * (1.f/H_);
        const float var  = sq * (1.f/H_) - mu*mu;
        const float rstd = rsqrtf(var + 1e-5f);
        #pragma unroll
        for (int i = 0; i < 8; i++) {
            const int c = lane + i*32;
            const float y = fmaf((src[r*H_ + c] - mu)*rstd, g[c], b[c]);
            if (OM == 0) {
                ((float*)dstv)[r*H_ + c] = y;
            } else {
                __half hi, lo; hilo16(y, hi, lo);
                __half* d = (__half*)dstv + r*LDA2;
                d[c] = hi; d[256 + c] = lo;
            }
        }
    }
}

// ---------------------------------------------------------------------------
// Attention: 2 warps per head (16 warps). Both warps of a pair compute the
// full score row (duplicated, cheap); the output dg loop is split.
// qkv fp32 in BUFf (ld LDQ); output hi/lo fp16 into XN2.
// ---------------------------------------------------------------------------
__device__ __forceinline__ void attn32(const float* BUFf, const __nv_bfloat16* BS,
                                       const float* KM, __half* XN2, int tid)
{
    const int w = tid >> 5, lane = tid & 31;
    const int head = w >> 1, half = w & 1;
    const float scale = 0.17677669529663687f;  // 1/sqrt(32)

    float4 q4[8];
    const float4* qp = (const float4*)(BUFf + lane*LDQ + head*32);
    #pragma unroll
    for (int j = 0; j < 8; j++) q4[j] = qp[j];

    float sc[32];
    float m = -3.0e38f;
    #pragma unroll
    for (int kr = 0; kr < 32; kr++) {
        const float4* kp = (const float4*)(BUFf + kr*LDQ + 256 + head*32);
        float s0 = 0.f, s1 = 0.f;   // two partial chains (shorter dep chain)
        #pragma unroll
        for (int j = 0; j < 8; j += 2) {
            const float4 k0 = kp[j], k1 = kp[j+1];
            s0 = fmaf(q4[j].x, k0.x, s0);   s0 = fmaf(q4[j].y, k0.y, s0);
            s0 = fmaf(q4[j].z, k0.z, s0);   s0 = fmaf(q4[j].w, k0.w, s0);
            s1 = fmaf(q4[j+1].x, k1.x, s1); s1 = fmaf(q4[j+1].y, k1.y, s1);
            s1 = fmaf(q4[j+1].z, k1.z, s1); s1 = fmaf(q4[j+1].w, k1.w, s1);
        }
        const float bv = __bfloat162float(BS[head*1024 + kr*32 + lane]);
        const float s = fmaf(s0 + s1, scale, bv) + KM[kr];
        sc[kr] = s;
        m = fmaxf(m, s);
    }
    float den = 0.f;
    #pragma unroll
    for (int kr = 0; kr < 32; kr++) { const float e = __expf(sc[kr] - m); sc[kr] = e; den += e; }
    const float inv = 1.f / den;
    #pragma unroll
    for (int kr = 0; kr < 32; kr++) sc[kr] *= inv;

    // output: this warp covers dg half*4 .. half*4+3 (16 d-columns per warp)
    #pragma unroll
    for (int dg = 0; dg < 4; dg++) {
        const int dgg = half*4 + dg;
        float4 acc = make_float4(0.f, 0.f, 0.f, 0.f);
        #pragma unroll
        for (int kr = 0; kr < 32; kr++) {
            const float4 v4 = *(const float4*)(BUFf + kr*LDQ + 512 + head*32 + dgg*4);
            const float wv = sc[kr];
            acc.x = fmaf(wv, v4.x, acc.x); acc.y = fmaf(wv, v4.y, acc.y);
            acc.z = fmaf(wv, v4.z, acc.z); acc.w = fmaf(wv, v4.w, acc.w);
        }
        const float av[4] = {acc.x, acc.y, acc.z, acc.w};
        __half* d = XN2 + lane*LDA2;
        #pragma unroll
        for (int e = 0; e < 4; e++) {
            const int c = head*32 + dgg*4 + e;
            __half hi, lo; hilo16(av[e], hi, lo);
            d[c] = hi; d[256 + c] = lo;
        }
    }
}

// ---------------------------------------------------------------------------
__global__ __launch_bounds__(THREADS, 1) void xf_kernel(
    const float* __restrict__ h, const void* __restrict__ validp,
    const float* __restrict__ ln1g, const float* __restrict__ ln1b,
    const float* __restrict__ qkvb, const float* __restrict__ outb,
    const float* __restrict__ ln2g, const float* __restrict__ ln2b,
    const float* __restrict__ ff1b, const float* __restrict__ ff2b,
    const float* __restrict__ fng, const float* __restrict__ fnb,
    float* __restrict__ out)
{
    extern __shared__ float sm[];
    float* X    = sm + OFF_X;
    float* BUFf = sm + OFF_BUF;
    __half* BUF2 = (__half*)(sm + OFF_BUF);
    __half* XN2  = (__half*)(sm + OFF_XN2);
    __nv_bfloat16* BS = (__nv_bfloat16*)(sm + OFF_BS);
    float* KM  = sm + OFF_KM;
    float* V01 = sm + OFF_V01;
    const int s = blockIdx.x, tid = threadIdx.x;

    // Detect 'valid' encoding: byte bools vs 32-bit words.
    const unsigned char* vb = (const unsigned char*)validp;
    bool bytemode = false;
    #pragma unroll
    for (int i = 1; i < 128; i += 4) bytemode |= (vb[i] != 0);

    if (tid < K_) {
        bool v;
        if (bytemode) v = vb[s*K_ + tid] != 0;
        else          v = ((const unsigned int*)validp)[s*K_ + tid] != 0u;
        KM[tid]  = v ? 0.f : -1e30f;
        V01[tid] = v ? 1.f : 0.f;
    }
    for (int i = tid; i < K_*H_/4; i += THREADS)
        ((float4*)X)[i] = ((const float4*)(h + (size_t)s*K_*H_))[i];
    {
        const uint4* gb = (const uint4*)(g_bias16 + (size_t)s*NH_*K_*K_);
        uint4* sb = (uint4*)BS;
        for (int i = tid; i < 1024; i += THREADS) sb[i] = gb[i];
    }
    __syncthreads();

    for (int l = 0; l < L_; l++) {
        ln32<1>(X, XN2, ln1g + l*H_, ln1b + l*H_, tid);
        __syncthreads();
        mm3<768, 256, 0>(XN2, LDA2, (const uint4*)(g_w2_qkv + (size_t)l*768*128),
                         qkvb + l*768, X, BUFf, BUF2, tid);
        __syncthreads();
        attn32(BUFf, BS, KM, XN2, tid);
        __syncthreads();
        mm3<256, 256, 2>(XN2, LDA2, (const uint4*)(g_w2_out + (size_t)l*256*128),
                         outb + l*H_, X, BUFf, BUF2, tid);
        __syncthreads();
        ln32<1>(X, XN2, ln2g + l*H_, ln2b + l*H_, tid);
        __syncthreads();
        mm3<512, 256, 1>(XN2, LDA2, (const uint4*)(g_w2_ff1 + (size_t)l*512*128),
                         ff1b + l*FFN_, X, BUFf, BUF2, tid);
        __syncthreads();
        mm3<256, 512, 2>(BUF2, LDB2, (const uint4*)(g_w2_ff2 + (size_t)l*256*256),
                         ff2b + l*H_, X, BUFf, BUF2, tid);
        __syncthreads();
    }

    // final LN (fp32 into BUFf region, ld H_) + masked mean over k
    ln32<0>(X, BUFf, fng, fnb, tid);
    __syncthreads();
    if (tid < H_) {
        float sum = 0.f, cnt = 0.f;
        #pragma unroll
        for (int r = 0; r < K_; r++) {
            sum = fmaf(BUFf[r*H_ + tid], V01[r], sum);
            cnt += V01[r];
        }
        out[(size_t)s*H_ + tid] = sum / fmaxf(cnt, 1.f);
    }
}

// ---------------------------------------------------------------------------
extern "C" void kernel_launch(void* const* d_in, const int* in_sizes, int n_in,
                              void* d_out, int out_size)
{
    // inputs: 0 h, 1 valid, 2 edge_index, 3 ea_flat, 4 edge_ptr, 5 S, 6 k,
    // 7 edge_W, 8 edge_b, 9 ln1_g, 10 ln1_b, 11 qkv_W, 12 qkv_b, 13 out_W,
    // 14 out_b, 15 ln2_g, 16 ln2_b, 17 ff1_W, 18 ff1_b, 19 ff2_W, 20 ff2_b,
    // 21 fnorm_g, 22 fnorm_b
    cudaFuncSetAttribute(xf_kernel, cudaFuncAttributeMaxDynamicSharedMemorySize,
                         SMEM_FLOATS * (int)sizeof(float));

    unsigned *w2_qkv, *w2_out, *w2_ff1, *w2_ff2;
    cudaGetSymbolAddress((void**)&w2_qkv, g_w2_qkv);
    cudaGetSymbolAddress((void**)&w2_out, g_w2_out);
    cudaGetSymbolAddress((void**)&w2_ff1, g_w2_ff1);
    cudaGetSymbolAddress((void**)&w2_ff2, g_w2_ff2);

    // total_units = L * N*KA/8 per gemm
    wconv_frag<<<(L_*768*256/8 + 255)/256, 256>>>(
        (const float*)d_in[11], (uint4*)w2_qkv, 768, 256, L_*768*256/8);
    wconv_frag<<<(L_*256*256/8 + 255)/256, 256>>>(
        (const float*)d_in[13], (uint4*)w2_out, 256, 256, L_*256*256/8);
    wconv_frag<<<(L_*512*256/8 + 255)/256, 256>>>(
        (const float*)d_in[17], (uint4*)w2_ff1, 512, 256, L_*512*256/8);
    wconv_frag<<<(L_*256*512/8 + 255)/256, 256>>>(
        (const float*)d_in[19], (uint4*)w2_ff2, 256, 512, L_*256*512/8);

    edge_bias_kernel<<<S_, 256>>>(
        (const float*)d_in[3], (const int*)d_in[2],
        (const float*)d_in[7], (const float*)d_in[8]);

    xf_kernel<<<S_, THREADS, SMEM_FLOATS * sizeof(float)>>>(
        (const float*)d_in[0], d_in[1],
        (const float*)d_in[9],  (const float*)d_in[10],
        (const float*)d_in[12], (const float*)d_in[14],
        (const float*)d_in[15], (const float*)d_in[16],
        (const float*)d_in[18], (const float*)d_in[20],
        (const float*)d_in[21], (const float*)d_in[22],
        (float*)d_out);
}

// round 17
// speedup vs baseline: 1.8239x; 1.8239x over previous
#include <cuda_runtime.h>
#include <cuda_bf16.h>
#include <cuda_fp16.h>
#include <math.h>

// Problem constants (LocalSubgraphTransformer)
#define S_   2048
#define K_   32
#define H_   256
#define NH_  8
#define DH_  32
#define L_   4
#define ED_  16
#define FFN_ 512
#define EPS_ 64
#define E_   (S_*EPS_)

#define LDA2 264    // XN2 row stride (fp16): 256 + 8 pad  (33 granules, mod 8 = 1)
#define LDB2 520    // BUF2 row stride (fp16): 512 + 8 pad (65 granules, mod 8 = 1)
#define LDQ  772    // qkv fp32 row stride

// ---------------- device scratch ----------------
__device__ __nv_bfloat16 g_bias16[(size_t)S_ * NH_ * K_ * K_];   // [S][h][k][q]
// weights in mma B-fragment order, single fp16: N*KA fp16 = N*KA/2 u32 words
__device__ unsigned g_w2_qkv[(size_t)L_ * 768 * 128];
__device__ unsigned g_w2_out[(size_t)L_ * 256 * 128];
__device__ unsigned g_w2_ff1[(size_t)L_ * 512 * 128];
__device__ unsigned g_w2_ff2[(size_t)L_ * 256 * 256];

// ---------------------------------------------------------------------------
// Weight conversion (all 4 tensors in ONE launch): fp32 [L][N][KA] row-major
// -> fp16 B-fragment layout. Unit (16 B) uid = (((pass*T+kt)*8+ng)*2+j)*32+lane
//   n = pass*128 + ng*16 + j*8 + (lane>>2)
//   word w: k = kt*32 + (w>>1)*16 + (lane&3)*2 + (w&1)*8, covers {k, k+1}
// ---------------------------------------------------------------------------
__device__ __forceinline__ void wconv_one(const float* __restrict__ src,
                                          uint4* __restrict__ dst,
                                          int N, int KA, int e)
{
    const int UPL = N*KA/8;            // units per layer
    const int l = e / UPL;
    int u = e - l*UPL;
    const int lane = u & 31; u >>= 5;
    const int j = u & 1; u >>= 1;
    const int ng = u & 7; u >>= 3;
    const int T = KA/32;
    const int kt = u % T;
    const int pass = u / T;
    const int n = pass*128 + ng*16 + j*8 + (lane>>2);
    const float* sp = src + ((size_t)l*N + n)*KA;

    unsigned words[4];
    #pragma unroll
    for (int w = 0; w < 4; w++) {
        const int k = kt*32 + (w>>1)*16 + (lane&3)*2 + (w&1)*8;
        const __half v0 = __float2half(sp[k]);
        const __half v1 = __float2half(sp[k+1]);
        unsigned lo16 = (unsigned)*(const unsigned short*)&v0;
        unsigned hi16 = (unsigned)*(const unsigned short*)&v1;
        words[w] = lo16 | (hi16 << 16);
    }
    dst[e] = make_uint4(words[0], words[1], words[2], words[3]);
}

#define U_QKV (L_*768*256/8)   /* 98304 */
#define U_OUT (L_*256*256/8)   /* 32768 */
#define U_FF1 (L_*512*256/8)   /* 65536 */
#define U_FF2 (L_*256*512/8)   /* 65536 */

__global__ void wconv_all(const float* __restrict__ s_qkv, const float* __restrict__ s_out,
                          const float* __restrict__ s_ff1, const float* __restrict__ s_ff2)
{
    int e = blockIdx.x*256 + threadIdx.x;
    if (e < U_QKV) { wconv_one(s_qkv, (uint4*)g_w2_qkv, 768, 256, e); return; }
    e -= U_QKV;
    if (e < U_OUT) { wconv_one(s_out, (uint4*)g_w2_out, 256, 256, e); return; }
    e -= U_OUT;
    if (e < U_FF1) { wconv_one(s_ff1, (uint4*)g_w2_ff1, 512, 256, e); return; }
    e -= U_FF1;
    if (e < U_FF2) { wconv_one(s_ff2, (uint4*)g_w2_ff2, 256, 512, e); return; }
}

// ---------------------------------------------------------------------------
// Kernel A: per-subgraph edge bias via shared-memory scatter-add
// ---------------------------------------------------------------------------
__global__ __launch_bounds__(256) void edge_bias_kernel(
    const float* __restrict__ ea, const int* __restrict__ eidx,
    const float* __restrict__ eW, const float* __restrict__ eb)
{
    __shared__ float sb[NH_*K_*K_];   // [h][dst=k][src=q]
    __shared__ float sa[EPS_*ED_];
    __shared__ float sw[NH_*ED_];
    __shared__ float sbv[NH_];
    const int s = blockIdx.x, tid = threadIdx.x;

    if (tid < NH_*ED_) sw[tid] = eW[tid];
    if (tid < NH_)     sbv[tid] = eb[tid];
    for (int i = tid; i < EPS_*ED_;  i += 256) sa[i] = ea[(size_t)s*EPS_*ED_ + i];
    for (int i = tid; i < NH_*K_*K_; i += 256) sb[i] = 0.f;
    __syncthreads();

    for (int t = tid; t < EPS_*NH_; t += 256) {
        const int i  = t >> 3;
        const int hh = t & 7;
        float p = sbv[hh];
        #pragma unroll
        for (int d = 0; d < ED_; d++) p = fmaf(sa[i*ED_+d], sw[hh*ED_+d], p);
        const int e  = s*EPS_ + i;
        const int sr = eidx[e];        // src = query index
        const int ds = eidx[E_ + e];   // dst = key index
        atomicAdd(&sb[hh*K_*K_ + ds*K_ + sr], p);
    }
    __syncthreads();
    for (int i = tid; i < NH_*K_*K_; i += 256)
        g_bias16[(size_t)s*NH_*K_*K_ + i] = __float2bfloat16(sb[i]);
}

// ---------------------------------------------------------------------------
// smem layout (float offsets)
// ---------------------------------------------------------------------------
#define OFF_X    0        /* 8192 f: X fp32 [32][256] */
#define OFF_BUF  8192     /* 24704 f: union { fp32 [32][772] qkv ; fp16 [32][520] ffn } */
#define OFF_XN2  32896    /* 4224 f: fp16 [32][264] */
#define OFF_BS   37120    /* 4096 f: bf16 [8][32][32] */
#define OFF_KM   41216
#define OFF_V01  41248
#define SMEM_FLOATS 41280  /* 165120 bytes */

__device__ __forceinline__ unsigned sptr(const void* p) {
    return (unsigned)__cvta_generic_to_shared(p);
}
__device__ __forceinline__ void ldm_x4(unsigned& a0, unsigned& a1, unsigned& a2,
                                       unsigned& a3, unsigned addr) {
    asm volatile("ldmatrix.sync.aligned.m8n8.x4.shared.b16 {%0,%1,%2,%3},[%4];"
                 : "=r"(a0), "=r"(a1), "=r"(a2), "=r"(a3) : "r"(addr));
}
__device__ __forceinline__ void mma16816h(float* c, const unsigned* a,
                                          unsigned b0, unsigned b1) {
    asm volatile("mma.sync.aligned.m16n8k16.row.col.f32.f16.f16.f32 "
                 "{%0,%1,%2,%3},{%4,%5,%6,%7},{%8,%9},{%0,%1,%2,%3};"
                 : "+f"(c[0]), "+f"(c[1]), "+f"(c[2]), "+f"(c[3])
                 : "r"(a[0]), "r"(a[1]), "r"(a[2]), "r"(a[3]), "r"(b0), "r"(b1));
}

// ---------------------------------------------------------------------------
// Tensor-core GEMM: C = A W^T + bias, fp16 operands, fp32 accum.
// A: smem fp16 [32][KA] (ld lda). W: gmem fp16 fragment layout.
// 8 warps, warp tile m32 x n16 (n-group = wid); passes in pairs (n256 blocks).
// B: 4-slot register ring over global step (pipelines across blocks).
// MODE 0: fp32 -> BUFf (ld LDQ); 1: relu -> fp16 BUF2; 2: += X (ld H_)
// ---------------------------------------------------------------------------
template<int N, int KA, int MODE>
__device__ __forceinline__ void mm3(const __half* A, int lda,
    const uint4* __restrict__ Wf, const float* __restrict__ bias,
    float* Xd, float* BUFf, __half* BUF2, int tid)
{
    const int lane = tid & 31, wid = tid >> 5;
    constexpr int T = KA/32;          // k32 stages per pass
    constexpr int NB = N/256;         // pass-pair blocks
    constexpr int TOT = NB*2*T;       // global steps
    // A ldmatrix base: row = lane&15, 16B col = lane>>4
    const unsigned a_s = sptr(A) + (unsigned)(((lane & 15)*lda + ((lane >> 4) << 3))*2);

    // 4-slot B ring; 2T is a multiple of 4, so slot = step & 3 globally.
    uint4 ring[4][2];
    #define LDB_G(sg, slot) do {                                                    \
        if ((sg) < TOT) {                                                           \
            const int _blk = (sg) / (2*T);                                          \
            const int _sl  = (sg) - _blk*2*T;                                       \
            const int _p = _sl & 1, _kt = _sl >> 1;                                 \
            const size_t _b = ((size_t)(((_blk*2 + _p)*T + _kt)*8 + wid)*2)*32 + lane; \
            ring[slot][0] = Wf[_b];  ring[slot][1] = Wf[_b + 32];                   \
        }                                                                           \
    } while (0)

    LDB_G(0, 0); LDB_G(1, 1); LDB_G(2, 2); LDB_G(3, 3);

    for (int blk = 0; blk < NB; blk++) {
        float acc[2][2][2][4];   // [p][mi][j][4]
        #pragma unroll
        for (int p = 0; p < 2; p++)
            #pragma unroll
            for (int mi = 0; mi < 2; mi++)
                #pragma unroll
                for (int j = 0; j < 2; j++)
                    #pragma unroll
                    for (int i = 0; i < 4; i++) acc[p][mi][j][i] = 0.f;

        const int g0 = blk*2*T;
        #pragma unroll
        for (int kt = 0; kt < T; kt++) {
            // A fragments: [mi][ks], single fp16 (4 x ldmatrix.x4)
            unsigned a[2][2][4];
            #pragma unroll
            for (int mi = 0; mi < 2; mi++)
                #pragma unroll
                for (int ks = 0; ks < 2; ks++) {
                    const unsigned base = a_s + (unsigned)((mi*16*lda + kt*32 + ks*16)*2);
                    ldm_x4(a[mi][ks][0], a[mi][ks][1], a[mi][ks][2], a[mi][ks][3], base);
                }
            // ---- step p=0: consume slot (2kt)&3, reload step +4 ----
            {
                const uint4* b = ring[(2*kt) & 3];
                #pragma unroll
                for (int mi = 0; mi < 2; mi++) {
                    mma16816h(acc[0][mi][0], a[mi][0], b[0].x, b[0].y);
                    mma16816h(acc[0][mi][1], a[mi][0], b[1].x, b[1].y);
                    mma16816h(acc[0][mi][0], a[mi][1], b[0].z, b[0].w);
                    mma16816h(acc[0][mi][1], a[mi][1], b[1].z, b[1].w);
                }
                LDB_G(g0 + 2*kt + 4, (2*kt) & 3);
            }
            // ---- step p=1: consume slot (2kt+1)&3, reload step +4 ----
            {
                const uint4* b = ring[(2*kt + 1) & 3];
                #pragma unroll
                for (int mi = 0; mi < 2; mi++) {
                    mma16816h(acc[1][mi][0], a[mi][0], b[0].x, b[0].y);
                    mma16816h(acc[1][mi][1], a[mi][0], b[1].x, b[1].y);
                    mma16816h(acc[1][mi][0], a[mi][1], b[0].z, b[0].w);
                    mma16816h(acc[1][mi][1], a[mi][1], b[1].z, b[1].w);
                }
                LDB_G(g0 + 2*kt + 5, (2*kt + 1) & 3);
            }
        }
        // epilogue
        #pragma unroll
        for (int p = 0; p < 2; p++)
            #pragma unroll
            for (int mi = 0; mi < 2; mi++)
                #pragma unroll
                for (int j = 0; j < 2; j++) {
                    const int c = (blk*2 + p)*128 + wid*16 + j*8 + 2*(lane & 3);
                    const float bb0 = bias[c], bb1 = bias[c+1];
                    #pragma unroll
                    for (int rr = 0; rr < 2; rr++) {
                        const int r = mi*16 + (lane >> 2) + rr*8;
                        float v0 = acc[p][mi][j][rr*2+0] + bb0;
                        float v1 = acc[p][mi][j][rr*2+1] + bb1;
                        if (MODE == 0) {
                            BUFf[r*LDQ + c]   = v0;
                            BUFf[r*LDQ + c+1] = v1;
                        } else if (MODE == 2) {
                            Xd[r*H_ + c]   += v0;
                            Xd[r*H_ + c+1] += v1;
                        } else {
                            v0 = fmaxf(v0, 0.f); v1 = fmaxf(v1, 0.f);
                            __half* d = BUF2 + r*LDB2;
                            d[c]   = __float2half(v0);
                            d[c+1] = __float2half(v1);
                        }
                    }
                }
    }
    #undef LDB_G
}

// ---------------------------------------------------------------------------
// LayerNorm over 32 rows. OM 0: fp32 dst (ld H_); OM 1: fp16 dst (ld LDA2)
// ---------------------------------------------------------------------------
template<int OM>
__device__ __forceinline__ void ln32(const float* src, void* dstv,
                                     const float* __restrict__ g,
                                     const float* __restrict__ b, int tid)
{
    const int w = tid >> 5, lane = tid & 31;
    #pragma unroll
    for (int j = 0; j < 4; j++) {
        const int r = w*4 + j;
        float sum = 0.f, sq = 0.f;
        #pragma unroll
        for (int i = 0; i < 8; i++) {
            const float v = src[r*H_ + lane + i*32];
            sum += v; sq = fmaf(v, v, sq);
        }
        #pragma unroll
        for (int o = 16; o > 0; o >>= 1) {
            sum += __shfl_xor_sync(0xffffffffu, sum, o);
            sq  += __shfl_xor_sync(0xffffffffu, sq,  o);
        }
        const float mu   = sum * (1.f/H_);
        const float var  = sq * (1.f/H_) - mu*mu;
        const float rstd = rsqrtf(var + 1e-5f);
        #pragma unroll
        for (int i = 0; i < 8; i++) {
            const int c = lane + i*32;
            const float y = fmaf((src[r*H_ + c] - mu)*rstd, g[c], b[c]);
            if (OM == 0) ((float*)dstv)[r*H_ + c] = y;
            else         ((__half*)dstv)[r*LDA2 + c] = __float2half(y);
        }
    }
}

// ---------------------------------------------------------------------------
// Attention: warp = head, lane = query row. qkv fp32 in BUFf (ld LDQ);
// output written as fp16 into XN2.
// ---------------------------------------------------------------------------
__device__ __forceinline__ void attn32(const float* BUFf, const __nv_bfloat16* BS,
                                       const float* KM, __half* XN2, int tid)
{
    const int head = tid >> 5, lane = tid & 31;
    const float scale = 0.17677669529663687f;  // 1/sqrt(32)

    float4 q4[8];
    const float4* qp = (const float4*)(BUFf + lane*LDQ + head*32);
    #pragma unroll
    for (int j = 0; j < 8; j++) q4[j] = qp[j];

    float sc[32];
    float m = -3.0e38f;
    #pragma unroll
    for (int kr = 0; kr < 32; kr++) {
        const float4* kp = (const float4*)(BUFf + kr*LDQ + 256 + head*32);
        float s0 = 0.f, s1 = 0.f;
        #pragma unroll
        for (int j = 0; j < 8; j += 2) {
            const float4 k0 = kp[j], k1 = kp[j+1];
            s0 = fmaf(q4[j].x, k0.x, s0);   s0 = fmaf(q4[j].y, k0.y, s0);
            s0 = fmaf(q4[j].z, k0.z, s0);   s0 = fmaf(q4[j].w, k0.w, s0);
            s1 = fmaf(q4[j+1].x, k1.x, s1); s1 = fmaf(q4[j+1].y, k1.y, s1);
            s1 = fmaf(q4[j+1].z, k1.z, s1); s1 = fmaf(q4[j+1].w, k1.w, s1);
        }
        const float bv = __bfloat162float(BS[head*1024 + kr*32 + lane]);
        const float s = fmaf(s0 + s1, scale, bv) + KM[kr];
        sc[kr] = s;
        m = fmaxf(m, s);
    }
    float den = 0.f;
    #pragma unroll
    for (int kr = 0; kr < 32; kr++) { const float e = __expf(sc[kr] - m); sc[kr] = e; den += e; }
    const float inv = 1.f / den;
    #pragma unroll
    for (int kr = 0; kr < 32; kr++) sc[kr] *= inv;

    #pragma unroll
    for (int dg = 0; dg < 8; dg++) {
        float4 acc = make_float4(0.f, 0.f, 0.f, 0.f);
        #pragma unroll
        for (int kr = 0; kr < 32; kr++) {
            const float4 v4 = *(const float4*)(BUFf + kr*LDQ + 512 + head*32 + dg*4);
            const float w = sc[kr];
            acc.x = fmaf(w, v4.x, acc.x); acc.y = fmaf(w, v4.y, acc.y);
            acc.z = fmaf(w, v4.z, acc.z); acc.w = fmaf(w, v4.w, acc.w);
        }
        const float av[4] = {acc.x, acc.y, acc.z, acc.w};
        __half* d = XN2 + lane*LDA2;
        #pragma unroll
        for (int e = 0; e < 4; e++)
            d[head*32 + dg*4 + e] = __float2half(av[e]);
    }
}

// ---------------------------------------------------------------------------
__global__ __launch_bounds__(256, 1) void xf_kernel(
    const float* __restrict__ h, const void* __restrict__ validp,
    const float* __restrict__ ln1g, const float* __restrict__ ln1b,
    const float* __restrict__ qkvb, const float* __restrict__ outb,
    const float* __restrict__ ln2g, const float* __restrict__ ln2b,
    const float* __restrict__ ff1b, const float* __restrict__ ff2b,
    const float* __restrict__ fng, const float* __restrict__ fnb,
    float* __restrict__ out)
{
    extern __shared__ float sm[];
    float* X    = sm + OFF_X;
    float* BUFf = sm + OFF_BUF;
    __half* BUF2 = (__half*)(sm + OFF_BUF);
    __half* XN2  = (__half*)(sm + OFF_XN2);
    __nv_bfloat16* BS = (__nv_bfloat16*)(sm + OFF_BS);
    float* KM  = sm + OFF_KM;
    float* V01 = sm + OFF_V01;
    const int s = blockIdx.x, tid = threadIdx.x;

    // Detect 'valid' encoding: byte bools vs 32-bit words.
    const unsigned char* vb = (const unsigned char*)validp;
    bool bytemode = false;
    #pragma unroll
    for (int i = 1; i < 128; i += 4) bytemode |= (vb[i] != 0);

    if (tid < K_) {
        bool v;
        if (bytemode) v = vb[s*K_ + tid] != 0;
        else          v = ((const unsigned int*)validp)[s*K_ + tid] != 0u;
        KM[tid]  = v ? 0.f : -1e30f;
        V01[tid] = v ? 1.f : 0.f;
    }
    for (int i = tid; i < K_*H_/4; i += 256)
        ((float4*)X)[i] = ((const float4*)(h + (size_t)s*K_*H_))[i];
    {
        const uint4* gb = (const uint4*)(g_bias16 + (size_t)s*NH_*K_*K_);
        uint4* sb = (uint4*)BS;
        for (int i = tid; i < 1024; i += 256) sb[i] = gb[i];
    }
    __syncthreads();

    for (int l = 0; l < L_; l++) {
        ln32<1>(X, XN2, ln1g + l*H_, ln1b + l*H_, tid);
        __syncthreads();
        mm3<768, 256, 0>(XN2, LDA2, (const uint4*)(g_w2_qkv + (size_t)l*768*128),
                         qkvb + l*768, X, BUFf, BUF2, tid);
        __syncthreads();
        attn32(BUFf, BS, KM, XN2, tid);
        __syncthreads();
        mm3<256, 256, 2>(XN2, LDA2, (const uint4*)(g_w2_out + (size_t)l*256*128),
                         outb + l*H_, X, BUFf, BUF2, tid);
        __syncthreads();
        ln32<1>(X, XN2, ln2g + l*H_, ln2b + l*H_, tid);
        __syncthreads();
        mm3<512, 256, 1>(XN2, LDA2, (const uint4*)(g_w2_ff1 + (size_t)l*512*128),
                         ff1b + l*FFN_, X, BUFf, BUF2, tid);
        __syncthreads();
        mm3<256, 512, 2>(BUF2, LDB2, (const uint4*)(g_w2_ff2 + (size_t)l*256*256),
                         ff2b + l*H_, X, BUFf, BUF2, tid);
        __syncthreads();
    }

    // final LN (fp32 into BUFf region, ld H_) + masked mean over k
    ln32<0>(X, BUFf, fng, fnb, tid);
    __syncthreads();
    float sum = 0.f, cnt = 0.f;
    #pragma unroll
    for (int r = 0; r < K_; r++) {
        sum = fmaf(BUFf[r*H_ + tid], V01[r], sum);
        cnt += V01[r];
    }
    out[(size_t)s*H_ + tid] = sum / fmaxf(cnt, 1.f);
}

// ---------------------------------------------------------------------------
extern "C" void kernel_launch(void* const* d_in, const int* in_sizes, int n_in,
                              void* d_out, int out_size)
{
    // inputs: 0 h, 1 valid, 2 edge_index, 3 ea_flat, 4 edge_ptr, 5 S, 6 k,
    // 7 edge_W, 8 edge_b, 9 ln1_g, 10 ln1_b, 11 qkv_W, 12 qkv_b, 13 out_W,
    // 14 out_b, 15 ln2_g, 16 ln2_b, 17 ff1_W, 18 ff1_b, 19 ff2_W, 20 ff2_b,
    // 21 fnorm_g, 22 fnorm_b
    cudaFuncSetAttribute(xf_kernel, cudaFuncAttributeMaxDynamicSharedMemorySize,
                         SMEM_FLOATS * (int)sizeof(float));

    const int total_units = U_QKV + U_OUT + U_FF1 + U_FF2;
    wconv_all<<<(total_units + 255)/256, 256>>>(
        (const float*)d_in[11], (const float*)d_in[13],
        (const float*)d_in[17], (const float*)d_in[19]);

    edge_bias_kernel<<<S_, 256>>>(
        (const float*)d_in[3], (const int*)d_in[2],
        (const float*)d_in[7], (const float*)d_in[8]);

    xf_kernel<<<S_, 256, SMEM_FLOATS * sizeof(float)>>>(
        (const float*)d_in[0], d_in[1],
        (const float*)d_in[9],  (const float*)d_in[10],
        (const float*)d_in[12], (const float*)d_in[14],
        (const float*)d_in[15], (const float*)d_in[16],
        (const float*)d_in[18], (const float*)d_in[20],
        (const float*)d_in[21], (const float*)d_in[22],
        (float*)d_out);
}